// round 13
// baseline (speedup 1.0000x reference)
#include <cuda_runtime.h>
#include <cuda_fp16.h>
#include <cstdint>

#define NN 100000
#define EE 1250000
#define HH 128
#define EPSBN 1e-5f
#define SCAN_B 1024
#define NB_SCAN ((NN + SCAN_B - 1) / SCAN_B)   // 98
#define KC 64
#define LDP (KC + 8)                            // 72 halves = 144B = 9*16B (16B-aligned rows)

// ---------------- static device scratch ----------------
__device__ int g_deg[NN];
__device__ int g_rowptr[NN + 1];
__device__ int g_fill[NN];
__device__ int g_csr[EE];
__device__ int g_bsums[NB_SCAN];
__device__ __align__(16) __half g_xf16[(size_t)NN * 64];
__device__ __align__(16) __half g_a16[(size_t)NN * HH];   // normalized act, layer 0 out
__device__ __align__(16) __half g_b16[(size_t)NN * HH];   // normalized act, layer 1 out
__device__ __align__(16) __half g_ng16[(size_t)NN * HH];  // aggregated neighbors
__device__ __align__(16) float  g_h32[(size_t)NN * HH];   // raw h (fp32, pre-BN)
__device__ __align__(16) __half g_wT0[HH * 128];
__device__ __align__(16) __half g_wT1[HH * 256];
__device__ __align__(16) __half g_wT2[HH * 256];
__device__ __align__(16) float g_colsum[HH];
__device__ __align__(16) float g_colsq[HH];

// ---------------- PTX helpers (non-'a' ISA only) ----------------
__device__ __forceinline__ uint32_t smem_u32(const void* p) {
    uint32_t a;
    asm("{ .reg .u64 t; cvta.to.shared.u64 t, %1; cvt.u32.u64 %0, t; }" : "=r"(a) : "l"(p));
    return a;
}
__device__ __forceinline__ void cp16(uint32_t saddr, const void* g) {
    asm volatile("cp.async.cg.shared.global [%0], [%1], 16;" :: "r"(saddr), "l"(g));
}
__device__ __forceinline__ void ldsm4(uint32_t* r, uint32_t addr) {
    asm volatile("ldmatrix.sync.aligned.m8n8.x4.shared.b16 {%0,%1,%2,%3}, [%4];"
                 : "=r"(r[0]), "=r"(r[1]), "=r"(r[2]), "=r"(r[3]) : "r"(addr));
}
__device__ __forceinline__ void mma16816(float* d, const uint32_t* a, const uint32_t* b) {
    asm volatile("mma.sync.aligned.m16n8k16.row.col.f32.f16.f16.f32 "
                 "{%0,%1,%2,%3}, {%4,%5,%6,%7}, {%8,%9}, {%0,%1,%2,%3};"
                 : "+f"(d[0]), "+f"(d[1]), "+f"(d[2]), "+f"(d[3])
                 : "r"(a[0]), "r"(a[1]), "r"(a[2]), "r"(a[3]), "r"(b[0]), "r"(b[1]));
}

// compute BN scale/shift into smem (threads 0..127 participate; caller syncs)
__device__ __forceinline__ void bn_scale_shift(int tid, const float* gamma, const float* beta,
                                               float* ssc, float* ssh) {
    if (tid < 128) {
        float s = g_colsum[tid], q = g_colsq[tid];
        const float invn = 1.0f / (float)NN;
        float mu = s * invn;
        float var = fmaxf(q * invn - mu * mu, 0.f);
        float r = rsqrtf(var + EPSBN);
        float sc = r * gamma[tid];
        ssc[tid] = sc;
        ssh[tid] = beta[tid] - mu * sc;
    }
}

// ---------------- zero for CSR counters (main stream, ahead of hist) ----------------
__global__ void k_zero() {
    int i = blockIdx.x * blockDim.x + threadIdx.x;
    if (i < NN) { g_deg[i] = 0; g_fill[i] = 0; }
}

// ---------------- prologue (side stream): BN acc zero + rowptr[NN] + x->fp16 + weight transposes --
__global__ void k_prologue(const float* __restrict__ x,
                           const float* __restrict__ Ws0, const float* __restrict__ Wn0,
                           const float* __restrict__ Ws1, const float* __restrict__ Wn1,
                           const float* __restrict__ Ws2, const float* __restrict__ Wn2) {
    size_t i = (size_t)blockIdx.x * blockDim.x + threadIdx.x;
    if (i < HH) { g_colsum[i] = 0.f; g_colsq[i] = 0.f; }
    if (i == 0) g_rowptr[NN] = EE;
    if (i < 81920) {
        const float* W; __half* o; int KTOT, k0, idx = (int)i;
        if (i < 8192)        { W = Ws0; o = g_wT0; KTOT = 128; k0 = 0; }
        else if (i < 16384)  { W = Wn0; o = g_wT0; KTOT = 128; k0 = 64;  idx -= 8192; }
        else if (i < 32768)  { W = Ws1; o = g_wT1; KTOT = 256; k0 = 0;   idx -= 16384; }
        else if (i < 49152)  { W = Wn1; o = g_wT1; KTOT = 256; k0 = 128; idx -= 32768; }
        else if (i < 65536)  { W = Ws2; o = g_wT2; KTOT = 256; k0 = 0;   idx -= 49152; }
        else                 { W = Wn2; o = g_wT2; KTOT = 256; k0 = 128; idx -= 65536; }
        int k = idx >> 7, n = idx & 127;
        o[(size_t)n * KTOT + k0 + k] = __float2half(W[(size_t)k * HH + n]);
    }
    if (i < (size_t)NN * 64 / 2) {
        float2 v = ((const float2*)x)[i];
        ((__half2*)g_xf16)[i] = __floats2half2_rn(v.x, v.y);
    }
}

// ---------------- CSR build ----------------
__global__ void k_hist(const int* __restrict__ dst) {
    int e = blockIdx.x * blockDim.x + threadIdx.x;
    if (e < EE) atomicAdd(&g_deg[dst[e]], 1);
}

__global__ void k_scan1() {
    __shared__ int s[SCAN_B];
    int tid = threadIdx.x;
    int i = blockIdx.x * SCAN_B + tid;
    int v = (i < NN) ? g_deg[i] : 0;
    s[tid] = v;
    __syncthreads();
    for (int off = 1; off < SCAN_B; off <<= 1) {
        int t = (tid >= off) ? s[tid - off] : 0;
        __syncthreads();
        s[tid] += t;
        __syncthreads();
    }
    if (i < NN) g_rowptr[i] = s[tid] - v;
    if (tid == SCAN_B - 1) g_bsums[blockIdx.x] = s[tid];   // raw block total
}

// scan2 folded in: each block computes its own bsums prefix with one warp
__global__ void k_scan23() {
    __shared__ int pref;
    int tid = threadIdx.x;
    if (tid < 32) {
        int t = 0;
        for (int j = tid; j < blockIdx.x; j += 32) t += g_bsums[j];
#pragma unroll
        for (int o = 16; o; o >>= 1) t += __shfl_xor_sync(0xFFFFFFFFu, t, o);
        if (tid == 0) pref = t;
    }
    __syncthreads();
    int i = blockIdx.x * SCAN_B + tid;
    if (i < NN) g_rowptr[i] += pref;
}

__global__ void k_fill(const int* __restrict__ src, const int* __restrict__ dst) {
    int e = blockIdx.x * blockDim.x + threadIdx.x;
    if (e < EE) {
        int d = dst[e];
        int p = atomicAdd(&g_fill[d], 1);
        g_csr[g_rowptr[d] + p] = src[e];
    }
}

// BN(scale/shift computed inline) + ReLU -> fp16 ; float4 reads
__global__ void k_cvt_bn(const float* __restrict__ h, const float* __restrict__ gamma,
                         const float* __restrict__ beta, __half* __restrict__ o) {
    __shared__ float ssc[128], ssh[128];
    int tid = threadIdx.x;
    bn_scale_shift(tid, gamma, beta, ssc, ssh);
    __syncthreads();
    size_t i = (size_t)blockIdx.x * blockDim.x + tid;   // float4 index
    if (i >= (size_t)NN * HH / 4) return;
    int c4 = ((int)(i & 31)) * 4;
    float4 v = ((const float4*)h)[i];
    float r0 = fmaxf(fmaf(v.x, ssc[c4 + 0], ssh[c4 + 0]), 0.f);
    float r1 = fmaxf(fmaf(v.y, ssc[c4 + 1], ssh[c4 + 1]), 0.f);
    float r2 = fmaxf(fmaf(v.z, ssc[c4 + 2], ssh[c4 + 2]), 0.f);
    float r3 = fmaxf(fmaf(v.w, ssc[c4 + 3], ssh[c4 + 3]), 0.f);
    __half2 h2[2] = {__floats2half2_rn(r0, r1), __floats2half2_rn(r2, r3)};
    ((uint2*)o)[i] = *(uint2*)h2;
}

// ---------------- mean aggregation: vectorized uint4 gathers, edge-slot split ----------------
template <int DIN>
__global__ void k_agg16(const __half* __restrict__ xin) {
    // reset BN accumulators for the following GEMM (stream-ordered after prior readers)
    if (blockIdx.x == 0 && threadIdx.x < 128) {
        g_colsum[threadIdx.x] = 0.f;
        g_colsq[threadIdx.x] = 0.f;
    }
    const int LPR = DIN / 8;
    const int EPW = 32 / LPR;
    int gw = (blockIdx.x * blockDim.x + threadIdx.x) >> 5;
    int lane = threadIdx.x & 31;
    if (gw >= NN) return;
    int off = lane & (LPR - 1);
    int sub = lane / LPR;
    int beg = g_rowptr[gw], end = g_rowptr[gw + 1];
    int deg = end - beg;
    int iters = (deg + EPW - 1) / EPW;            // warp-uniform
    float acc[8];
#pragma unroll
    for (int j = 0; j < 8; j++) acc[j] = 0.f;
    int e = beg + sub;
#pragma unroll 4
    for (int it = 0; it < iters; it++, e += EPW) {
        uint4 v = make_uint4(0u, 0u, 0u, 0u);
        if (e < end)
            v = *(const uint4*)(xin + (size_t)__ldg(&g_csr[e]) * DIN + off * 8);
        const __half2* hv = (const __half2*)&v;
#pragma unroll
        for (int j = 0; j < 4; j++) {
            float2 f = __half22float2(hv[j]);
            acc[2 * j] += f.x;
            acc[2 * j + 1] += f.y;
        }
    }
    // combine edge slots
#pragma unroll
    for (int st = LPR; st < 32; st <<= 1) {
#pragma unroll
        for (int j = 0; j < 8; j++)
            acc[j] += __shfl_xor_sync(0xFFFFFFFFu, acc[j], st);
    }
    float inv = (deg > 0) ? 1.0f / (float)deg : 0.f;
    if (sub == 0) {
        __half2 h2[4];
#pragma unroll
        for (int j = 0; j < 4; j++)
            h2[j] = __floats2half2_rn(acc[2 * j] * inv, acc[2 * j + 1] * inv);
        *(uint4*)(g_ng16 + (size_t)gw * DIN + off * 8) = *(uint4*)h2;
    }
}

// ---------------- HMMA GEMM: 256-row tiles, 512 thr (16 warps, 8m x 2n), cp.async 2-stage ------
// h[256 tile][128] = [X | Ng] @ wT' + bias, fused BN stats.
template <int KTOT>
__launch_bounds__(512, 1)
__global__ void k_gemm_hmma(const __half* __restrict__ xf, const __half* __restrict__ ngf,
                            const __half* __restrict__ wT, const float* __restrict__ bias,
                            float* __restrict__ hout) {
    const int DIN = KTOT / 2;
    const int ATILE = 256 * LDP;                 // halves
    const int BTILE = 128 * LDP;
    extern __shared__ char dsm[];
    __half* sA0 = (__half*)dsm;
    __half* sA1 = sA0 + ATILE;
    __half* sB0 = sA1 + ATILE;
    __half* sB1 = sB0 + BTILE;
    float* sbias = (float*)(sB1 + BTILE);
    float* sstat = sbias + HH;                   // 256 floats

    int tid = threadIdx.x, lane = tid & 31, wid = tid >> 5;
    int wm = wid & 7, wn = wid >> 3;
    int n0 = blockIdx.x * 256;
    if (tid < HH) sbias[tid] = bias[tid];
    if (tid < 256) sstat[tid] = 0.f;

    float acc[2][8][4];
#pragma unroll
    for (int am = 0; am < 2; am++)
#pragma unroll
        for (int an = 0; an < 8; an++)
#pragma unroll
            for (int j = 0; j < 4; j++) acc[am][an][j] = 0.f;

    int aRow = wm * 32 + (lane & 15);
    int aCol = (lane >> 4) * 8;
    int bRow = wn * 64 + ((lane >> 4) << 3) + (lane & 7);
    int bCol = ((lane >> 3) & 1) * 8;
    const int NCH = KTOT / KC;

    auto load_chunk = [&](int ch, __half* dA, __half* dB) {
        int kc0 = ch * KC;
        const __half* asrc = (kc0 < DIN) ? (xf + kc0) : (ngf + (kc0 - DIN));
        for (int i = tid; i < 256 * 8; i += 512) {
            int row = i >> 3, c8 = (i & 7) * 8;
            int gn = min(n0 + row, NN - 1);
            cp16(smem_u32(dA + row * LDP + c8), asrc + (size_t)gn * DIN + c8);
        }
        for (int i = tid; i < 128 * 8; i += 512) {
            int row = i >> 3, c8 = (i & 7) * 8;
            cp16(smem_u32(dB + row * LDP + c8), wT + (size_t)row * KTOT + kc0 + c8);
        }
    };

    load_chunk(0, sA0, sB0);
    asm volatile("cp.async.commit_group;" ::: "memory");

    for (int ch = 0; ch < NCH; ch++) {
        __half* cA = (ch & 1) ? sA1 : sA0;
        __half* cB = (ch & 1) ? sB1 : sB0;
        if (ch + 1 < NCH) {
            load_chunk(ch + 1, (ch & 1) ? sA0 : sA1, (ch & 1) ? sB0 : sB1);
            asm volatile("cp.async.commit_group;" ::: "memory");
            asm volatile("cp.async.wait_group 1;" ::: "memory");
        } else {
            asm volatile("cp.async.wait_group 0;" ::: "memory");
        }
        __syncthreads();
#pragma unroll
        for (int kk = 0; kk < KC; kk += 16) {
            uint32_t a[2][4];
#pragma unroll
            for (int am = 0; am < 2; am++)
                ldsm4(a[am], smem_u32(cA + (aRow + am * 16) * LDP + kk + aCol));
            uint32_t b[8][2];
#pragma unroll
            for (int bi = 0; bi < 4; bi++) {
                uint32_t r[4];
                ldsm4(r, smem_u32(cB + (bRow + bi * 16) * LDP + kk + bCol));
                b[2 * bi][0] = r[0]; b[2 * bi][1] = r[1];
                b[2 * bi + 1][0] = r[2]; b[2 * bi + 1][1] = r[3];
            }
#pragma unroll
            for (int am = 0; am < 2; am++)
#pragma unroll
                for (int an = 0; an < 8; an++)
                    mma16816(acc[am][an], a[am], b[an]);
        }
        __syncthreads();
    }

    // epilogue: bias + fp32 store + BN stats (shuffle reduce, few smem atomics)
    int r0 = wm * 32 + (lane >> 2);
    int c0 = wn * 64 + (lane & 3) * 2;
#pragma unroll
    for (int an = 0; an < 8; an++) {
        int c = c0 + an * 8;
        float b0 = sbias[c], b1 = sbias[c + 1];
        float s0 = 0.f, s1 = 0.f, q0 = 0.f, q1 = 0.f;
#pragma unroll
        for (int am = 0; am < 2; am++) {
            int gr = n0 + r0 + am * 16;
            if (gr < NN) {
                float o0 = acc[am][an][0] + b0, o1 = acc[am][an][1] + b1;
                *(float2*)(hout + (size_t)gr * HH + c) = make_float2(o0, o1);
                s0 += o0; s1 += o1; q0 += o0 * o0; q1 += o1 * o1;
            }
            if (gr + 8 < NN) {
                float o0 = acc[am][an][2] + b0, o1 = acc[am][an][3] + b1;
                *(float2*)(hout + (size_t)(gr + 8) * HH + c) = make_float2(o0, o1);
                s0 += o0; s1 += o1; q0 += o0 * o0; q1 += o1 * o1;
            }
        }
#pragma unroll
        for (int o = 4; o <= 16; o <<= 1) {
            s0 += __shfl_xor_sync(0xFFFFFFFFu, s0, o);
            s1 += __shfl_xor_sync(0xFFFFFFFFu, s1, o);
            q0 += __shfl_xor_sync(0xFFFFFFFFu, q0, o);
            q1 += __shfl_xor_sync(0xFFFFFFFFu, q1, o);
        }
        if (lane < 4) {
            atomicAdd(&sstat[c], s0);
            atomicAdd(&sstat[c + 1], s1);
            atomicAdd(&sstat[128 + c], q0);
            atomicAdd(&sstat[128 + c + 1], q1);
        }
    }
    __syncthreads();
    if (tid < 128) atomicAdd(&g_colsum[tid], sstat[tid]);
    else if (tid < 256) atomicAdd(&g_colsq[tid - 128], sstat[tid]);
}

// ---------------- classifier: reads raw fp32 h, BN inline, warp per node ----------------
__global__ void k_cls32(const float* __restrict__ h, const float* __restrict__ gamma,
                        const float* __restrict__ beta, const float* __restrict__ Wc,
                        const float* __restrict__ bc, float* __restrict__ out) {
    __shared__ float ssc[128], ssh[128], swc[256];
    int tid = threadIdx.x;
    bn_scale_shift(tid, gamma, beta, ssc, ssh);
    swc[tid] = Wc[tid];            // blockDim == 256 == HH*2
    __syncthreads();
    int gw = (blockIdx.x * blockDim.x + tid) >> 5;
    int lane = tid & 31;
    if (gw >= NN) return;
    float4 f = *(const float4*)(h + (size_t)gw * HH + 4 * lane);
    int k = 4 * lane;
    float v0 = fmaxf(fmaf(f.x, ssc[k + 0], ssh[k + 0]), 0.f);
    float v1 = fmaxf(fmaf(f.y, ssc[k + 1], ssh[k + 1]), 0.f);
    float v2 = fmaxf(fmaf(f.z, ssc[k + 2], ssh[k + 2]), 0.f);
    float v3 = fmaxf(fmaf(f.w, ssc[k + 3], ssh[k + 3]), 0.f);
    float a0 = v0 * swc[(k + 0) * 2] + v1 * swc[(k + 1) * 2] +
               v2 * swc[(k + 2) * 2] + v3 * swc[(k + 3) * 2];
    float a1 = v0 * swc[(k + 0) * 2 + 1] + v1 * swc[(k + 1) * 2 + 1] +
               v2 * swc[(k + 2) * 2 + 1] + v3 * swc[(k + 3) * 2 + 1];
#pragma unroll
    for (int o = 16; o; o >>= 1) {
        a0 += __shfl_xor_sync(0xFFFFFFFFu, a0, o);
        a1 += __shfl_xor_sync(0xFFFFFFFFu, a1, o);
    }
    if (lane == 0) {
        out[(size_t)gw * 2 + 0] = a0 + __ldg(&bc[0]);
        out[(size_t)gw * 2 + 1] = a1 + __ldg(&bc[1]);
    }
}

// ---------------- launch ----------------
extern "C" void kernel_launch(void* const* d_in, const int* in_sizes, int n_in,
                              void* d_out, int out_size) {
    const float* x   = (const float*)d_in[0];
    const int*   src = (const int*)d_in[1];
    const int*   dst = (const int*)d_in[2];
    const float* Ws0 = (const float*)d_in[3];
    const float* bs0 = (const float*)d_in[4];
    const float* Wn0 = (const float*)d_in[5];
    const float* ga0 = (const float*)d_in[6];
    const float* be0 = (const float*)d_in[7];
    const float* Ws1 = (const float*)d_in[8];
    const float* bs1 = (const float*)d_in[9];
    const float* Wn1 = (const float*)d_in[10];
    const float* ga1 = (const float*)d_in[11];
    const float* be1 = (const float*)d_in[12];
    const float* Ws2 = (const float*)d_in[13];
    const float* bs2 = (const float*)d_in[14];
    const float* Wn2 = (const float*)d_in[15];
    const float* ga2 = (const float*)d_in[16];
    const float* be2 = (const float*)d_in[17];
    const float* Wc  = (const float*)d_in[18];
    const float* bc  = (const float*)d_in[19];
    float* out = (float*)d_out;

    void* p;
    cudaGetSymbolAddress(&p, g_xf16); __half* xf16 = (__half*)p;
    cudaGetSymbolAddress(&p, g_a16);  __half* a16  = (__half*)p;
    cudaGetSymbolAddress(&p, g_b16);  __half* b16  = (__half*)p;
    cudaGetSymbolAddress(&p, g_ng16); __half* ng16 = (__half*)p;
    cudaGetSymbolAddress(&p, g_h32);  float*  h32  = (float*)p;
    cudaGetSymbolAddress(&p, g_wT0);  __half* wT0  = (__half*)p;
    cudaGetSymbolAddress(&p, g_wT1);  __half* wT1  = (__half*)p;
    cudaGetSymbolAddress(&p, g_wT2);  __half* wT2  = (__half*)p;

    // dynamic smem: 2 A-tiles (256*LDP) + 2 B-tiles (128*LDP) halves + bias + stat
    const int SMEM = (2 * 256 + 2 * 128) * LDP * 2 + (HH + 256) * 4;   // 112128 B
    cudaFuncSetAttribute(k_gemm_hmma<128>, cudaFuncAttributeMaxDynamicSharedMemorySize, SMEM);
    cudaFuncSetAttribute(k_gemm_hmma<256>, cudaFuncAttributeMaxDynamicSharedMemorySize, SMEM);

    const int TB = 256;

    // fork: prologue (weights/x) on side stream, CSR build on main stream
    cudaStream_t s2;
    cudaEvent_t e1, e2;
    cudaStreamCreateWithFlags(&s2, cudaStreamNonBlocking);
    cudaEventCreateWithFlags(&e1, cudaEventDisableTiming);
    cudaEventCreateWithFlags(&e2, cudaEventDisableTiming);

    cudaEventRecord(e1, 0);
    cudaStreamWaitEvent(s2, e1, 0);
    k_prologue<<<(NN * 64 / 2 + TB - 1) / TB, TB, 0, s2>>>(x, Ws0, Wn0, Ws1, Wn1, Ws2, Wn2);
    cudaEventRecord(e2, s2);

    k_zero<<<(NN + TB - 1) / TB, TB>>>();
    k_hist<<<(EE + TB - 1) / TB, TB>>>(dst);
    k_scan1<<<NB_SCAN, SCAN_B>>>();
    k_scan23<<<NB_SCAN, SCAN_B>>>();
    k_fill<<<(EE + TB - 1) / TB, TB>>>(src, dst);

    cudaStreamWaitEvent(0, e2, 0);   // join prologue before layer 0

    const int AGG_BLK  = (NN * 32 + TB - 1) / TB;   // warp per node
    const int GEMM_BLK = (NN + 255) / 256;          // 391
    const int CVT_BLK  = (NN * HH / 4 + TB - 1) / TB;

    // layer 0 (Din=64, K'=128)
    k_agg16<64><<<AGG_BLK, TB>>>(xf16);
    k_gemm_hmma<128><<<GEMM_BLK, 512, SMEM>>>(xf16, ng16, wT0, bs0, h32);
    k_cvt_bn<<<CVT_BLK, TB>>>(h32, ga0, be0, a16);

    // layer 1 (Din=128, K'=256)
    k_agg16<128><<<AGG_BLK, TB>>>(a16);
    k_gemm_hmma<256><<<GEMM_BLK, 512, SMEM>>>(a16, ng16, wT1, bs1, h32);
    k_cvt_bn<<<CVT_BLK, TB>>>(h32, ga1, be1, b16);

    // layer 2 (Din=128, K'=256)
    k_agg16<128><<<AGG_BLK, TB>>>(b16);
    k_gemm_hmma<256><<<GEMM_BLK, 512, SMEM>>>(b16, ng16, wT2, bs2, h32);

    // classifier: BN2 inline on fp32 h
    k_cls32<<<AGG_BLK, TB>>>(h32, ga2, be2, Wc, bc, out);

    cudaStreamDestroy(s2);
    cudaEventDestroy(e1);
    cudaEventDestroy(e2);
}

// round 15
// speedup vs baseline: 1.0347x; 1.0347x over previous
#include <cuda_runtime.h>
#include <cuda_fp16.h>
#include <cstdint>

#define NN 100000
#define EE 1250000
#define HH 128
#define EPSBN 1e-5f
#define SCAN_B 1024
#define NB_SCAN ((NN + SCAN_B - 1) / SCAN_B)   // 98
#define KC 64
#define LDP (KC + 8)                            // 72 halves = 144B = 9*16B (16B-aligned rows)

// ---------------- static device scratch ----------------
__device__ int g_deg[NN];
__device__ int g_rowptr[NN + 1];
__device__ int g_fill[NN];
__device__ int g_csr[EE];
__device__ int g_bsums[NB_SCAN];
__device__ __align__(16) __half g_xf16[(size_t)NN * 64];
__device__ __align__(16) __half g_a16[(size_t)NN * HH];   // normalized act, layer 0 out
__device__ __align__(16) __half g_b16[(size_t)NN * HH];   // normalized act, layer 1 out
__device__ __align__(16) __half g_ng16[(size_t)NN * HH];  // aggregated neighbors
__device__ __align__(16) float  g_h32[(size_t)NN * HH];   // raw h (fp32, pre-BN)
__device__ __align__(16) __half g_wT0[HH * 128];
__device__ __align__(16) __half g_wT1[HH * 256];
__device__ __align__(16) __half g_wT2[HH * 256];
__device__ __align__(16) float g_colsum[HH];
__device__ __align__(16) float g_colsq[HH];

// ---------------- PTX helpers (non-'a' ISA only) ----------------
__device__ __forceinline__ uint32_t smem_u32(const void* p) {
    uint32_t a;
    asm("{ .reg .u64 t; cvta.to.shared.u64 t, %1; cvt.u32.u64 %0, t; }" : "=r"(a) : "l"(p));
    return a;
}
__device__ __forceinline__ void cp16(uint32_t saddr, const void* g) {
    asm volatile("cp.async.cg.shared.global [%0], [%1], 16;" :: "r"(saddr), "l"(g));
}
__device__ __forceinline__ void ldsm4(uint32_t* r, uint32_t addr) {
    asm volatile("ldmatrix.sync.aligned.m8n8.x4.shared.b16 {%0,%1,%2,%3}, [%4];"
                 : "=r"(r[0]), "=r"(r[1]), "=r"(r[2]), "=r"(r[3]) : "r"(addr));
}
__device__ __forceinline__ void mma16816(float* d, const uint32_t* a, const uint32_t* b) {
    asm volatile("mma.sync.aligned.m16n8k16.row.col.f32.f16.f16.f32 "
                 "{%0,%1,%2,%3}, {%4,%5,%6,%7}, {%8,%9}, {%0,%1,%2,%3};"
                 : "+f"(d[0]), "+f"(d[1]), "+f"(d[2]), "+f"(d[3])
                 : "r"(a[0]), "r"(a[1]), "r"(a[2]), "r"(a[3]), "r"(b[0]), "r"(b[1]));
}

// compute BN scale/shift into smem (threads 0..127 participate; caller syncs)
__device__ __forceinline__ void bn_scale_shift(int tid, const float* gamma, const float* beta,
                                               float* ssc, float* ssh) {
    if (tid < 128) {
        float s = g_colsum[tid], q = g_colsq[tid];
        const float invn = 1.0f / (float)NN;
        float mu = s * invn;
        float var = fmaxf(q * invn - mu * mu, 0.f);
        float r = rsqrtf(var + EPSBN);
        float sc = r * gamma[tid];
        ssc[tid] = sc;
        ssh[tid] = beta[tid] - mu * sc;
    }
}

// ---------------- fused prologue: init + x->fp16 + all weight transposes ----------------
__global__ void k_prologue(const float* __restrict__ x,
                           const float* __restrict__ Ws0, const float* __restrict__ Wn0,
                           const float* __restrict__ Ws1, const float* __restrict__ Wn1,
                           const float* __restrict__ Ws2, const float* __restrict__ Wn2) {
    size_t i = (size_t)blockIdx.x * blockDim.x + threadIdx.x;
    if (i < NN) g_deg[i] = 0;
    if (i < HH) { g_colsum[i] = 0.f; g_colsq[i] = 0.f; }
    if (i == 0) g_rowptr[NN] = EE;
    if (i < 81920) {
        const float* W; __half* o; int KTOT, k0, idx = (int)i;
        if (i < 8192)        { W = Ws0; o = g_wT0; KTOT = 128; k0 = 0; }
        else if (i < 16384)  { W = Wn0; o = g_wT0; KTOT = 128; k0 = 64;  idx -= 8192; }
        else if (i < 32768)  { W = Ws1; o = g_wT1; KTOT = 256; k0 = 0;   idx -= 16384; }
        else if (i < 49152)  { W = Wn1; o = g_wT1; KTOT = 256; k0 = 128; idx -= 32768; }
        else if (i < 65536)  { W = Ws2; o = g_wT2; KTOT = 256; k0 = 0;   idx -= 49152; }
        else                 { W = Wn2; o = g_wT2; KTOT = 256; k0 = 128; idx -= 65536; }
        int k = idx >> 7, n = idx & 127;
        o[(size_t)n * KTOT + k0 + k] = __float2half(W[(size_t)k * HH + n]);
    }
    if (i < (size_t)NN * 64 / 2) {
        float2 v = ((const float2*)x)[i];
        ((__half2*)g_xf16)[i] = __floats2half2_rn(v.x, v.y);
    }
}

// ---------------- CSR build ----------------
__global__ void k_hist(const int* __restrict__ dst) {
    int e = blockIdx.x * blockDim.x + threadIdx.x;
    if (e < EE) atomicAdd(&g_deg[dst[e]], 1);
}

__global__ void k_scan1() {
    __shared__ int s[SCAN_B];
    int tid = threadIdx.x;
    int i = blockIdx.x * SCAN_B + tid;
    int v = (i < NN) ? g_deg[i] : 0;
    s[tid] = v;
    __syncthreads();
    for (int off = 1; off < SCAN_B; off <<= 1) {
        int t = (tid >= off) ? s[tid - off] : 0;
        __syncthreads();
        s[tid] += t;
        __syncthreads();
    }
    if (i < NN) g_rowptr[i] = s[tid] - v;
    if (tid == SCAN_B - 1) g_bsums[blockIdx.x] = s[tid];   // raw block total
}

// scan2 folded in; also seeds g_fill with the absolute rowptr (write cursor)
__global__ void k_scan23() {
    __shared__ int pref;
    int tid = threadIdx.x;
    if (tid < 32) {
        int t = 0;
        for (int j = tid; j < blockIdx.x; j += 32) t += g_bsums[j];
#pragma unroll
        for (int o = 16; o; o >>= 1) t += __shfl_xor_sync(0xFFFFFFFFu, t, o);
        if (tid == 0) pref = t;
    }
    __syncthreads();
    int i = blockIdx.x * SCAN_B + tid;
    if (i < NN) {
        int v = g_rowptr[i] + pref;
        g_rowptr[i] = v;
        g_fill[i] = v;         // write cursor = row start
    }
}

__global__ void k_fill(const int* __restrict__ src, const int* __restrict__ dst) {
    int e = blockIdx.x * blockDim.x + threadIdx.x;
    if (e < EE) {
        int p = atomicAdd(&g_fill[dst[e]], 1);
        g_csr[p] = src[e];
    }
}

// BN(scale/shift computed inline) + ReLU -> fp16 ; float4 reads
__global__ void k_cvt_bn(const float* __restrict__ h, const float* __restrict__ gamma,
                         const float* __restrict__ beta, __half* __restrict__ o) {
    __shared__ float ssc[128], ssh[128];
    int tid = threadIdx.x;
    bn_scale_shift(tid, gamma, beta, ssc, ssh);
    __syncthreads();
    size_t i = (size_t)blockIdx.x * blockDim.x + tid;   // float4 index
    if (i >= (size_t)NN * HH / 4) return;
    int c4 = ((int)(i & 31)) * 4;
    float4 v = ((const float4*)h)[i];
    float r0 = fmaxf(fmaf(v.x, ssc[c4 + 0], ssh[c4 + 0]), 0.f);
    float r1 = fmaxf(fmaf(v.y, ssc[c4 + 1], ssh[c4 + 1]), 0.f);
    float r2 = fmaxf(fmaf(v.z, ssc[c4 + 2], ssh[c4 + 2]), 0.f);
    float r3 = fmaxf(fmaf(v.w, ssc[c4 + 3], ssh[c4 + 3]), 0.f);
    __half2 h2[2] = {__floats2half2_rn(r0, r1), __floats2half2_rn(r2, r3)};
    ((uint2*)o)[i] = *(uint2*)h2;
}

// ---------------- mean aggregation: vectorized uint4 gathers, edge-slot split ----------------
template <int DIN>
__global__ void k_agg16(const __half* __restrict__ xin) {
    // reset BN accumulators for the following GEMM (stream-ordered after prior readers)
    if (blockIdx.x == 0 && threadIdx.x < 128) {
        g_colsum[threadIdx.x] = 0.f;
        g_colsq[threadIdx.x] = 0.f;
    }
    const int LPR = DIN / 8;
    const int EPW = 32 / LPR;
    int gw = (blockIdx.x * blockDim.x + threadIdx.x) >> 5;
    int lane = threadIdx.x & 31;
    if (gw >= NN) return;
    int off = lane & (LPR - 1);
    int sub = lane / LPR;
    int beg = g_rowptr[gw], end = g_rowptr[gw + 1];
    int deg = end - beg;
    int iters = (deg + EPW - 1) / EPW;            // warp-uniform
    float acc[8];
#pragma unroll
    for (int j = 0; j < 8; j++) acc[j] = 0.f;
    int e = beg + sub;
#pragma unroll 4
    for (int it = 0; it < iters; it++, e += EPW) {
        uint4 v = make_uint4(0u, 0u, 0u, 0u);
        if (e < end)
            v = *(const uint4*)(xin + (size_t)__ldg(&g_csr[e]) * DIN + off * 8);
        const __half2* hv = (const __half2*)&v;
#pragma unroll
        for (int j = 0; j < 4; j++) {
            float2 f = __half22float2(hv[j]);
            acc[2 * j] += f.x;
            acc[2 * j + 1] += f.y;
        }
    }
    // combine edge slots
#pragma unroll
    for (int st = LPR; st < 32; st <<= 1) {
#pragma unroll
        for (int j = 0; j < 8; j++)
            acc[j] += __shfl_xor_sync(0xFFFFFFFFu, acc[j], st);
    }
    float inv = (deg > 0) ? 1.0f / (float)deg : 0.f;
    if (sub == 0) {
        __half2 h2[4];
#pragma unroll
        for (int j = 0; j < 4; j++)
            h2[j] = __floats2half2_rn(acc[2 * j] * inv, acc[2 * j + 1] * inv);
        *(uint4*)(g_ng16 + (size_t)gw * DIN + off * 8) = *(uint4*)h2;
    }
}

// ---------------- HMMA GEMM: 128-row tiles, 256 thr (8 warps, 4m x 2n), cp.async 2-stage, occ 2 --
// h[128 tile][128] = [X | Ng] @ wT' + bias, fused BN stats.
template <int KTOT>
__launch_bounds__(256, 2)
__global__ void k_gemm_hmma(const __half* __restrict__ xf, const __half* __restrict__ ngf,
                            const __half* __restrict__ wT, const float* __restrict__ bias,
                            float* __restrict__ hout) {
    const int DIN = KTOT / 2;
    const int TILEH = 128 * LDP;                 // 9216 halves per tile
    extern __shared__ char dsm[];
    __half* sA0 = (__half*)dsm;
    __half* sB0 = sA0 + TILEH;
    __half* sA1 = sB0 + TILEH;
    __half* sB1 = sA1 + TILEH;
    float* sbias = (float*)(sB1 + TILEH);        // base + 4*TILEH halves = byte 73728
    float* sstat = sbias + HH;                   // 256 floats

    int tid = threadIdx.x, lane = tid & 31, wid = tid >> 5;
    int wm = wid & 3, wn = wid >> 2;
    int n0 = blockIdx.x * 128;
    if (tid < HH) sbias[tid] = bias[tid];
    sstat[tid] = 0.f;

    float acc[2][8][4];
#pragma unroll
    for (int am = 0; am < 2; am++)
#pragma unroll
        for (int an = 0; an < 8; an++)
#pragma unroll
            for (int j = 0; j < 4; j++) acc[am][an][j] = 0.f;

    int aRow = wm * 32 + (lane & 15);
    int aCol = (lane >> 4) * 8;
    int bRow = wn * 64 + ((lane >> 4) << 3) + (lane & 7);
    int bCol = ((lane >> 3) & 1) * 8;
    const int NCH = KTOT / KC;

    auto load_chunk = [&](int ch, __half* dA, __half* dB) {
        int kc0 = ch * KC;
        const __half* asrc = (kc0 < DIN) ? (xf + kc0) : (ngf + (kc0 - DIN));
        for (int i = tid; i < 128 * 8; i += 256) {
            int row = i >> 3, c8 = (i & 7) * 8;
            int gn = min(n0 + row, NN - 1);
            cp16(smem_u32(dA + row * LDP + c8), asrc + (size_t)gn * DIN + c8);
            cp16(smem_u32(dB + row * LDP + c8), wT + (size_t)row * KTOT + kc0 + c8);
        }
    };

    load_chunk(0, sA0, sB0);
    asm volatile("cp.async.commit_group;" ::: "memory");

    for (int ch = 0; ch < NCH; ch++) {
        __half* cA = (ch & 1) ? sA1 : sA0;
        __half* cB = (ch & 1) ? sB1 : sB0;
        if (ch + 1 < NCH) {
            load_chunk(ch + 1, (ch & 1) ? sA0 : sA1, (ch & 1) ? sB0 : sB1);
            asm volatile("cp.async.commit_group;" ::: "memory");
            asm volatile("cp.async.wait_group 1;" ::: "memory");
        } else {
            asm volatile("cp.async.wait_group 0;" ::: "memory");
        }
        __syncthreads();
#pragma unroll
        for (int kk = 0; kk < KC; kk += 16) {
            uint32_t a[2][4];
#pragma unroll
            for (int am = 0; am < 2; am++)
                ldsm4(a[am], smem_u32(cA + (aRow + am * 16) * LDP + kk + aCol));
            uint32_t b[8][2];
#pragma unroll
            for (int bi = 0; bi < 4; bi++) {
                uint32_t r[4];
                ldsm4(r, smem_u32(cB + (bRow + bi * 16) * LDP + kk + bCol));
                b[2 * bi][0] = r[0]; b[2 * bi][1] = r[1];
                b[2 * bi + 1][0] = r[2]; b[2 * bi + 1][1] = r[3];
            }
#pragma unroll
            for (int am = 0; am < 2; am++)
#pragma unroll
                for (int an = 0; an < 8; an++)
                    mma16816(acc[am][an], a[am], b[an]);
        }
        __syncthreads();
    }

    // epilogue: bias + fp32 store + BN stats (shuffle reduce, few smem atomics)
    int r0 = wm * 32 + (lane >> 2);
    int c0 = wn * 64 + (lane & 3) * 2;
#pragma unroll
    for (int an = 0; an < 8; an++) {
        int c = c0 + an * 8;
        float b0 = sbias[c], b1 = sbias[c + 1];
        float s0 = 0.f, s1 = 0.f, q0 = 0.f, q1 = 0.f;
#pragma unroll
        for (int am = 0; am < 2; am++) {
            int gr = n0 + r0 + am * 16;
            if (gr < NN) {
                float o0 = acc[am][an][0] + b0, o1 = acc[am][an][1] + b1;
                *(float2*)(hout + (size_t)gr * HH + c) = make_float2(o0, o1);
                s0 += o0; s1 += o1; q0 += o0 * o0; q1 += o1 * o1;
            }
            if (gr + 8 < NN) {
                float o0 = acc[am][an][2] + b0, o1 = acc[am][an][3] + b1;
                *(float2*)(hout + (size_t)(gr + 8) * HH + c) = make_float2(o0, o1);
                s0 += o0; s1 += o1; q0 += o0 * o0; q1 += o1 * o1;
            }
        }
#pragma unroll
        for (int o = 4; o <= 16; o <<= 1) {
            s0 += __shfl_xor_sync(0xFFFFFFFFu, s0, o);
            s1 += __shfl_xor_sync(0xFFFFFFFFu, s1, o);
            q0 += __shfl_xor_sync(0xFFFFFFFFu, q0, o);
            q1 += __shfl_xor_sync(0xFFFFFFFFu, q1, o);
        }
        if (lane < 4) {
            atomicAdd(&sstat[c], s0);
            atomicAdd(&sstat[c + 1], s1);
            atomicAdd(&sstat[128 + c], q0);
            atomicAdd(&sstat[128 + c + 1], q1);
        }
    }
    __syncthreads();
    if (tid < 128) atomicAdd(&g_colsum[tid], sstat[tid]);
    else atomicAdd(&g_colsq[tid - 128], sstat[tid]);
}

// ---------------- classifier: reads raw fp32 h, BN inline, warp per node ----------------
__global__ void k_cls32(const float* __restrict__ h, const float* __restrict__ gamma,
                        const float* __restrict__ beta, const float* __restrict__ Wc,
                        const float* __restrict__ bc, float* __restrict__ out) {
    __shared__ float ssc[128], ssh[128], swc[256];
    int tid = threadIdx.x;
    bn_scale_shift(tid, gamma, beta, ssc, ssh);
    swc[tid] = Wc[tid];            // blockDim == 256 == HH*2
    __syncthreads();
    int gw = (blockIdx.x * blockDim.x + tid) >> 5;
    int lane = tid & 31;
    if (gw >= NN) return;
    float4 f = *(const float4*)(h + (size_t)gw * HH + 4 * lane);
    int k = 4 * lane;
    float v0 = fmaxf(fmaf(f.x, ssc[k + 0], ssh[k + 0]), 0.f);
    float v1 = fmaxf(fmaf(f.y, ssc[k + 1], ssh[k + 1]), 0.f);
    float v2 = fmaxf(fmaf(f.z, ssc[k + 2], ssh[k + 2]), 0.f);
    float v3 = fmaxf(fmaf(f.w, ssc[k + 3], ssh[k + 3]), 0.f);
    float a0 = v0 * swc[(k + 0) * 2] + v1 * swc[(k + 1) * 2] +
               v2 * swc[(k + 2) * 2] + v3 * swc[(k + 3) * 2];
    float a1 = v0 * swc[(k + 0) * 2 + 1] + v1 * swc[(k + 1) * 2 + 1] +
               v2 * swc[(k + 2) * 2 + 1] + v3 * swc[(k + 3) * 2 + 1];
#pragma unroll
    for (int o = 16; o; o >>= 1) {
        a0 += __shfl_xor_sync(0xFFFFFFFFu, a0, o);
        a1 += __shfl_xor_sync(0xFFFFFFFFu, a1, o);
    }
    if (lane == 0) {
        out[(size_t)gw * 2 + 0] = a0 + __ldg(&bc[0]);
        out[(size_t)gw * 2 + 1] = a1 + __ldg(&bc[1]);
    }
}

// ---------------- launch (single stream; no fork) ----------------
extern "C" void kernel_launch(void* const* d_in, const int* in_sizes, int n_in,
                              void* d_out, int out_size) {
    const float* x   = (const float*)d_in[0];
    const int*   src = (const int*)d_in[1];
    const int*   dst = (const int*)d_in[2];
    const float* Ws0 = (const float*)d_in[3];
    const float* bs0 = (const float*)d_in[4];
    const float* Wn0 = (const float*)d_in[5];
    const float* ga0 = (const float*)d_in[6];
    const float* be0 = (const float*)d_in[7];
    const float* Ws1 = (const float*)d_in[8];
    const float* bs1 = (const float*)d_in[9];
    const float* Wn1 = (const float*)d_in[10];
    const float* ga1 = (const float*)d_in[11];
    const float* be1 = (const float*)d_in[12];
    const float* Ws2 = (const float*)d_in[13];
    const float* bs2 = (const float*)d_in[14];
    const float* Wn2 = (const float*)d_in[15];
    const float* ga2 = (const float*)d_in[16];
    const float* be2 = (const float*)d_in[17];
    const float* Wc  = (const float*)d_in[18];
    const float* bc  = (const float*)d_in[19];
    float* out = (float*)d_out;

    void* p;
    cudaGetSymbolAddress(&p, g_xf16); __half* xf16 = (__half*)p;
    cudaGetSymbolAddress(&p, g_a16);  __half* a16  = (__half*)p;
    cudaGetSymbolAddress(&p, g_b16);  __half* b16  = (__half*)p;
    cudaGetSymbolAddress(&p, g_ng16); __half* ng16 = (__half*)p;
    cudaGetSymbolAddress(&p, g_h32);  float*  h32  = (float*)p;
    cudaGetSymbolAddress(&p, g_wT0);  __half* wT0  = (__half*)p;
    cudaGetSymbolAddress(&p, g_wT1);  __half* wT1  = (__half*)p;
    cudaGetSymbolAddress(&p, g_wT2);  __half* wT2  = (__half*)p;

    // dynamic smem: 4 tiles of 128*LDP halves + bias(128f) + stat(256f) = 75264 B
    const int SMEM = 4 * 128 * LDP * 2 + (HH + 256) * 4;
    cudaFuncSetAttribute(k_gemm_hmma<128>, cudaFuncAttributeMaxDynamicSharedMemorySize, SMEM);
    cudaFuncSetAttribute(k_gemm_hmma<256>, cudaFuncAttributeMaxDynamicSharedMemorySize, SMEM);

    const int TB = 256;
    k_prologue<<<(NN * 64 / 2 + TB - 1) / TB, TB>>>(x, Ws0, Wn0, Ws1, Wn1, Ws2, Wn2);
    k_hist<<<(EE + TB - 1) / TB, TB>>>(dst);
    k_scan1<<<NB_SCAN, SCAN_B>>>();
    k_scan23<<<NB_SCAN, SCAN_B>>>();
    k_fill<<<(EE + TB - 1) / TB, TB>>>(src, dst);

    const int AGG_BLK  = (NN * 32 + TB - 1) / TB;   // warp per node
    const int GEMM_BLK = (NN + 127) / 128;          // 782
    const int CVT_BLK  = (NN * HH / 4 + TB - 1) / TB;

    // layer 0 (Din=64, K'=128)
    k_agg16<64><<<AGG_BLK, TB>>>(xf16);
    k_gemm_hmma<128><<<GEMM_BLK, TB, SMEM>>>(xf16, ng16, wT0, bs0, h32);
    k_cvt_bn<<<CVT_BLK, TB>>>(h32, ga0, be0, a16);

    // layer 1 (Din=128, K'=256)
    k_agg16<128><<<AGG_BLK, TB>>>(a16);
    k_gemm_hmma<256><<<GEMM_BLK, TB, SMEM>>>(a16, ng16, wT1, bs1, h32);
    k_cvt_bn<<<CVT_BLK, TB>>>(h32, ga1, be1, b16);

    // layer 2 (Din=128, K'=256)
    k_agg16<128><<<AGG_BLK, TB>>>(b16);
    k_gemm_hmma<256><<<GEMM_BLK, TB, SMEM>>>(b16, ng16, wT2, bs2, h32);

    // classifier: BN2 inline on fp32 h
    k_cls32<<<AGG_BLK, TB>>>(h32, ga2, be2, Wc, bc, out);
}